// round 13
// baseline (speedup 1.0000x reference)
#include <cuda_runtime.h>
#include <cuda_bf16.h>
#include <cstdint>

#define KDIM 16384
#define NB 8
#define NC 256
#define NKCLUST 16
#define SPLITS 5
#define KC 64
#define TILEB 16384              // one 128x64 bf16 tile (128B rows)
#define STGB  (2 * TILEB)        // X,Y per stage = 32KB
#define NSTAGE 3
#define SM_TOTAL (NSTAGE * STGB) // 96KB -> 2 CTAs/SM
#define GT 256

// ---------------- scratch ----------------
__device__ __nv_bfloat16 g_hi[NB][NC][KDIM];
__device__ __nv_bfloat16 g_lo[NB][NC][KDIM];
__device__ float  g_hh[SPLITS][NB][NC][NC];    // hh tiles (0,0),(0,1),(1,1)
__device__ float  g_M [SPLITS][NB][NC][NC];    // M = H·L^T, all 4 tiles
__device__ float  g_G[NB][NC][NC];
__device__ double g_rowpart[9][8][NC];
__device__ int    g_sel[NB][NKCLUST];
__device__ int    g_selpos[NKCLUST];

__device__ __forceinline__ uint32_t smem_u32(const void* p) {
    uint32_t a;
    asm("{ .reg .u64 t; cvta.to.shared.u64 t, %1; cvt.u32.u64 %0, t; }" : "=r"(a) : "l"(p));
    return a;
}
__device__ __forceinline__ uint32_t sw128(uint32_t off) { return off ^ ((off >> 3) & 0x70); }

#define CP_ASYNC16(dst, src) \
    asm volatile("cp.async.cg.shared.global [%0], [%1], 16;" :: "r"(dst), "l"(src))
#define CP_COMMIT() asm volatile("cp.async.commit_group;" ::: "memory")
#define CP_WAIT(N)  asm volatile("cp.async.wait_group %0;" :: "n"(N) : "memory")

#define LDSM4(r, addr) \
    asm volatile("ldmatrix.sync.aligned.m8n8.x4.shared.b16 {%0,%1,%2,%3}, [%4];" \
                 : "=r"((r)[0]), "=r"((r)[1]), "=r"((r)[2]), "=r"((r)[3]) : "r"(addr))

__device__ __forceinline__ void mma16816(float* c, const uint32_t* a, const uint32_t* b) {
    asm volatile("mma.sync.aligned.m16n8k16.row.col.f32.bf16.bf16.f32 "
                 "{%0,%1,%2,%3}, {%4,%5,%6,%7}, {%8,%9}, {%0,%1,%2,%3};"
                 : "+f"(c[0]), "+f"(c[1]), "+f"(c[2]), "+f"(c[3])
                 : "r"(a[0]), "r"(a[1]), "r"(a[2]), "r"(a[3]), "r"(b[0]), "r"(b[1]));
}

// ---------------- Kernel D: dummy (ncu slot alignment) ----------------
__global__ void dummy_kernel() {}

// ---------------- Kernel 0: fp32 -> bf16 hi/lo split ----------------
__global__ void __launch_bounds__(256) convert_kernel(const float* __restrict__ A) {
    size_t gid = (size_t)blockIdx.x * 256 + threadIdx.x;
    size_t base = gid * 8;
    float4 v0 = *reinterpret_cast<const float4*>(A + base);
    float4 v1 = *reinterpret_cast<const float4*>(A + base + 4);
    __nv_bfloat162 h[4];
    h[0] = __float22bfloat162_rn(make_float2(v0.x, v0.y));
    h[1] = __float22bfloat162_rn(make_float2(v0.z, v0.w));
    h[2] = __float22bfloat162_rn(make_float2(v1.x, v1.y));
    h[3] = __float22bfloat162_rn(make_float2(v1.z, v1.w));
    float2 f0 = __bfloat1622float2(h[0]), f1 = __bfloat1622float2(h[1]);
    float2 f2 = __bfloat1622float2(h[2]), f3 = __bfloat1622float2(h[3]);
    __nv_bfloat162 l[4];
    l[0] = __float22bfloat162_rn(make_float2(v0.x - f0.x, v0.y - f0.y));
    l[1] = __float22bfloat162_rn(make_float2(v0.z - f1.x, v0.w - f1.y));
    l[2] = __float22bfloat162_rn(make_float2(v1.x - f2.x, v1.y - f2.y));
    l[3] = __float22bfloat162_rn(make_float2(v1.z - f3.x, v1.w - f3.y));
    *reinterpret_cast<uint4*>(&g_hi[0][0][0] + base) = *reinterpret_cast<uint4*>(h);
    *reinterpret_cast<uint4*>(&g_lo[0][0][0] + base) = *reinterpret_cast<uint4*>(l);
}

// ---------------- Kernel 1: 7-product Gram (hh sym + M full) ---------------
// grid (7, SPLITS, NB), block 256 (8 warps 2x4, warp tile 64x32), 2 CTAs/SM.
// p: 0 hh(0,0) 1 hh(0,1) 2 hh(1,1) 3 M(0,0) 4 M(0,1) 5 M(1,0) 6 M(1,1)
__global__ void __launch_bounds__(GT, 2) gram_mma(int unused) {
    extern __shared__ char smem[];
    uint32_t smb = smem_u32(smem);
    int p = blockIdx.x, s = blockIdx.y, b = blockIdx.z;
    const int xi_t[7] = {0, 0, 1, 0, 0, 1, 1};
    const int yj_t[7] = {0, 1, 1, 0, 1, 0, 1};
    int xi = xi_t[p], yj = yj_t[p];
    bool useLo  = (p >= 3);
    bool sameXY = (p == 0 || p == 2);   // hh diagonal: Y tile == X tile

    const __nv_bfloat16* Xr = &g_hi[b][xi * 128][0];
    const __nv_bfloat16* Yr = useLo ? &g_lo[b][yj * 128][0] : &g_hi[b][yj * 128][0];

    int kb = ((s * KDIM) / SPLITS) & ~63;
    int ke = (((s + 1) * KDIM) / SPLITS) & ~63;
    if (s == SPLITS - 1) ke = KDIM;
    int n = (ke - kb) / KC;

    int t = threadIdx.x, l = t & 31, wid = t >> 5;
    int wr = wid >> 2, wc = wid & 3;        // 2x4 warps, warp tile 64x32

    int lrow = t >> 1;                      // 0..127
    int lseg = (t & 1) * 4;                 // 4 16B segs/thread/tile

    float acc[4][4][4];
#pragma unroll
    for (int f = 0; f < 4; f++)
#pragma unroll
        for (int g = 0; g < 4; g++)
#pragma unroll
            for (int q = 0; q < 4; q++) acc[f][g][q] = 0.0f;

    int mL = l & 15;
    int kaA = ((l >> 4) & 1) * 16;
    int nL = (l & 7) + ((l >> 4) & 1) * 8;
    int kaB = ((l >> 3) & 1) * 16;
    uint32_t arow[4], brow[2];
#pragma unroll
    for (int f = 0; f < 4; f++) arow[f] = (uint32_t)((wr * 64 + f * 16 + mL) * 128 + kaA);
#pragma unroll
    for (int g2 = 0; g2 < 2; g2++) brow[g2] = (uint32_t)((wc * 32 + g2 * 16 + nL) * 128 + kaB);

    auto load_chunk = [&](int c) {
        if (c < n) {
            int k0 = kb + c * KC;
            uint32_t base = smb + (uint32_t)(c % NSTAGE) * STGB;
            const __nv_bfloat16* srcX = Xr + (size_t)lrow * KDIM + k0 + lseg * 8;
            uint32_t d0 = sw128((uint32_t)(lrow * 128 + (lseg + 0) * 16));
            uint32_t d1 = sw128((uint32_t)(lrow * 128 + (lseg + 1) * 16));
            uint32_t d2 = sw128((uint32_t)(lrow * 128 + (lseg + 2) * 16));
            uint32_t d3 = sw128((uint32_t)(lrow * 128 + (lseg + 3) * 16));
            CP_ASYNC16(base + d0, srcX);
            CP_ASYNC16(base + d1, srcX + 8);
            CP_ASYNC16(base + d2, srcX + 16);
            CP_ASYNC16(base + d3, srcX + 24);
            if (!sameXY) {
                const __nv_bfloat16* srcY = Yr + (size_t)lrow * KDIM + k0 + lseg * 8;
                CP_ASYNC16(base + TILEB + d0, srcY);
                CP_ASYNC16(base + TILEB + d1, srcY + 8);
                CP_ASYNC16(base + TILEB + d2, srcY + 16);
                CP_ASYNC16(base + TILEB + d3, srcY + 24);
            }
        }
        CP_COMMIT();
    };

    load_chunk(0);
    load_chunk(1);

    for (int c = 0; c < n; c++) {
        CP_WAIT(1);
        __syncthreads();        // chunk c visible; all warps' mma(c-1) done
        load_chunk(c + 2);      // stage (c+2)%3 == (c-1)%3, safe now

        uint32_t base = smb + (uint32_t)(c % NSTAGE) * STGB;
        uint32_t Xb = base;
        uint32_t Yb = sameXY ? base : base + TILEB;
#pragma unroll
        for (int kk = 0; kk < 4; kk++) {
            uint32_t by_[2][4];
#pragma unroll
            for (int g2 = 0; g2 < 2; g2++)
                LDSM4(by_[g2], Yb + sw128(brow[g2] + kk * 32));
#pragma unroll
            for (int f = 0; f < 4; f++) {
                uint32_t ax_[4];
                LDSM4(ax_, Xb + sw128(arow[f] + kk * 32));
#pragma unroll
                for (int g = 0; g < 4; g++)
                    mma16816(acc[f][g], ax_, &by_[g >> 1][(g & 1) * 2]);
            }
        }
        // (no trailing barrier: next iteration's top barrier provides ordering)
    }

    float* outArr = (p < 3) ? &g_hh[s][b][0][0] : &g_M[s][b][0][0];
#pragma unroll
    for (int f = 0; f < 4; f++)
#pragma unroll
        for (int g = 0; g < 4; g++) {
            int m = wr * 64 + f * 16 + (l >> 2);
            int nn = wc * 32 + g * 8 + (l & 3) * 2;
            int gm = xi * 128 + m, gn = yj * 128 + nn;
            *reinterpret_cast<float2*>(outArr + gm * 256 + gn) =
                make_float2(acc[f][g][0], acc[f][g][1]);
            *reinterpret_cast<float2*>(outArr + (gm + 8) * 256 + gn) =
                make_float2(acc[f][g][2], acc[f][g][3]);
        }
}

// ---------------- Kernel 2: reduction  G = hh(sym) + M + M^T --------------
__global__ void __launch_bounds__(256) reduce_kernel() {
    int gid = blockIdx.x * 256 + threadIdx.x;
    int b  = gid >> 16;
    int ij = gid & 65535;
    int i  = ij >> 8;
    int j  = ij & 255;
    int si = i, sj = j;
    if (i >= 128 && j < 128) { si = j; sj = i; }   // canonical pair
    float acc = 0.0f;
#pragma unroll
    for (int s = 0; s < SPLITS; s++)
        acc += g_hh[s][b][si][sj] + g_M[s][b][si][sj] + g_M[s][b][sj][si];
    g_G[b][i][j] = acc;   // bitwise symmetric by construction
}

// ---------------- Kernel 2b: parallel row sums ----------------
__global__ void __launch_bounds__(256) rowsum_kernel(const float* __restrict__ pos) {
    int mode = blockIdx.x;
    int part = blockIdx.y;
    int j = threadIdx.x;
    double acc = 0.0;
    if (mode == 0) {
        float px = pos[j * 3 + 0], py = pos[j * 3 + 1], pz = pos[j * 3 + 2];
        float pn = px * px + py * py + pz * pz;
        for (int i = part * 32; i < part * 32 + 32; i++) {
            float qx = pos[i * 3 + 0], qy = pos[i * 3 + 1], qz = pos[i * 3 + 2];
            float qn = qx * qx + qy * qy + qz * qz;
            float d2 = qn + pn - 2.0f * (qx * px + qy * py + qz * pz);
            acc += (double)sqrtf(fmaxf(d2, 0.0f));
        }
    } else {
        const float* Gb = &g_G[mode - 1][0][0];
        float nj = Gb[j * 256 + j];
        for (int i = part * 32; i < part * 32 + 32; i++) {
            float d2 = Gb[i * 256 + i] + nj - 2.0f * Gb[i * 256 + j];
            acc += (double)sqrtf(fmaxf(d2, 0.0f));
        }
    }
    g_rowpart[mode][part][j] = acc;
}

// ---------------- Kernel 3: farthest point sampling ----------------
__global__ void __launch_bounds__(256) fps_kernel(const float* __restrict__ pos) {
    int j = threadIdx.x;
    int mode = blockIdx.x;
    __shared__ double sdv[256];
    __shared__ int    sidx[256];
    __shared__ float  spx[256], spy[256], spz[256], snrm[256];
    __shared__ int    ssel[NKCLUST];

    const float* Gb = nullptr;
    if (mode == 0) {
        spx[j] = pos[j * 3 + 0]; spy[j] = pos[j * 3 + 1]; spz[j] = pos[j * 3 + 2];
    } else {
        Gb = &g_G[mode - 1][0][0];
    }
    __syncthreads();
    if (mode == 0) snrm[j] = spx[j] * spx[j] + spy[j] * spy[j] + spz[j] * spz[j];
    else           snrm[j] = Gb[j * 256 + j];
    __syncthreads();

    auto dist = [&](int i) -> float {
        float d2;
        if (mode == 0) {
            float dot = spx[i] * spx[j] + spy[i] * spy[j] + spz[i] * spz[j];
            d2 = snrm[i] + snrm[j] - 2.0f * dot;
        } else {
            d2 = snrm[i] + snrm[j] - 2.0f * Gb[i * 256 + j];
        }
        return sqrtf(fmaxf(d2, 0.0f));
    };

    double rs = 0.0;
#pragma unroll
    for (int p = 0; p < 8; p++) rs += g_rowpart[mode][p][j];
    sdv[j] = rs; sidx[j] = j;
    __syncthreads();
    for (int off = 128; off > 0; off >>= 1) {
        if (j < off) {
            double v2 = sdv[j + off]; int i2 = sidx[j + off];
            if (v2 > sdv[j] || (v2 == sdv[j] && i2 < sidx[j])) { sdv[j] = v2; sidx[j] = i2; }
        }
        __syncthreads();
    }
    int cur = sidx[0];
    __syncthreads();
    if (j == 0) ssel[0] = cur;
    float mind = dist(cur);

    for (int it = 1; it < NKCLUST; it++) {
        sdv[j] = (double)mind; sidx[j] = j;
        __syncthreads();
        for (int off = 128; off > 0; off >>= 1) {
            if (j < off) {
                double v2 = sdv[j + off]; int i2 = sidx[j + off];
                if (v2 > sdv[j] || (v2 == sdv[j] && i2 < sidx[j])) { sdv[j] = v2; sidx[j] = i2; }
            }
            __syncthreads();
        }
        cur = sidx[0];
        __syncthreads();
        if (j == 0) ssel[it] = cur;
        mind = fminf(mind, dist(cur));
    }
    __syncthreads();
    if (j < NKCLUST) {
        if (mode == 0) g_selpos[j] = ssel[j];
        else           g_sel[mode - 1][j] = ssel[j];
    }
}

// ---------------- Kernel 4: fused assign + update + final ----------------
__global__ void __launch_bounds__(512) tail_kernel(const float* __restrict__ pos,
                                                   float* __restrict__ out) {
    __shared__ float spos[NB * NC * 3];
    __shared__ float scx[NB][NKCLUST], scy[NB][NKCLUST], scz[NB][NKCLUST], scn[NB][NKCLUST];
    __shared__ int   sta[NB * NC];
    __shared__ float ax[NKCLUST], ay[NKCLUST], az[NKCLUST], an[NKCLUST];
    __shared__ float fcx[NKCLUST], fcy[NKCLUST], fcz[NKCLUST], fcn[NKCLUST];
    __shared__ unsigned char sord[256][NKCLUST];
    __shared__ int scounts[NKCLUST];

    int t = threadIdx.x;
    for (int i = t; i < NB * NC * 3; i += 512) spos[i] = pos[i];
    if (t < NKCLUST) scounts[t] = 0;
    __syncthreads();

    if (t < NB * NKCLUST) {
        int b = t >> 4, k = t & 15;
        int si = g_sel[b][k];
        float x = spos[(b * 256 + si) * 3 + 0];
        float y = spos[(b * 256 + si) * 3 + 1];
        float z = spos[(b * 256 + si) * 3 + 2];
        scx[b][k] = x; scy[b][k] = y; scz[b][k] = z; scn[b][k] = x * x + y * y + z * z;
    }
    __syncthreads();

    for (int p = t; p < NB * NC; p += 512) {
        int b = p >> 8;
        float px = spos[p * 3 + 0], py = spos[p * 3 + 1], pz = spos[p * 3 + 2];
        float pn = px * px + py * py + pz * pz;
        float best = 1e30f; int bi = 0;
        for (int k = 0; k < NKCLUST; k++) {
            float d2 = pn + scn[b][k] - 2.0f * (px * scx[b][k] + py * scy[b][k] + pz * scz[b][k]);
            float d = sqrtf(fmaxf(d2, 0.0f));
            if (d < best) { best = d; bi = k; }
        }
        sta[p] = bi;
    }
    __syncthreads();

    int wid = t >> 5, l = t & 31;
    if (wid < NKCLUST) {
        float sx = 0.f, sy = 0.f, sz = 0.f, cnt = 0.f;
        for (int p = l; p < NB * NC; p += 32) {
            if (sta[p] == wid) {
                sx += spos[p * 3 + 0]; sy += spos[p * 3 + 1]; sz += spos[p * 3 + 2];
                cnt += 1.0f;
            }
        }
#pragma unroll
        for (int off = 16; off > 0; off >>= 1) {
            sx  += __shfl_down_sync(0xffffffffu, sx,  off);
            sy  += __shfl_down_sync(0xffffffffu, sy,  off);
            sz  += __shfl_down_sync(0xffffffffu, sz,  off);
            cnt += __shfl_down_sync(0xffffffffu, cnt, off);
        }
        if (l == 0) {
            if (cnt > 0.f) {
                float dn = fmaxf(cnt, 1.0f);
                ax[wid] = sx / dn; ay[wid] = sy / dn; az[wid] = sz / dn;
            } else { ax[wid] = 0.f; ay[wid] = 0.f; az[wid] = 0.f; }
            an[wid] = ax[wid] * ax[wid] + ay[wid] * ay[wid] + az[wid] * az[wid];
        }
    }
    __syncthreads();

    if (t < NKCLUST) {
        int si = g_selpos[t];
        float cx = spos[si * 3 + 0], cy = spos[si * 3 + 1], cz = spos[si * 3 + 2];
        float cnrm = cx * cx + cy * cy + cz * cz;
        float best = 1e30f; int bm = 0;
        for (int m = 0; m < NKCLUST; m++) {
            float d2 = cnrm + an[m] - 2.0f * (cx * ax[m] + cy * ay[m] + cz * az[m]);
            float d = sqrtf(fmaxf(d2, 0.0f));
            if (d < best) { best = d; bm = m; }
        }
        float nx = 0.8f * cx + 0.2f * ax[bm];
        float ny = 0.8f * cy + 0.2f * ay[bm];
        float nz = 0.8f * cz + 0.2f * az[bm];
        fcx[t] = nx; fcy[t] = ny; fcz[t] = nz; fcn[t] = nx * nx + ny * ny + nz * nz;
    }
    __syncthreads();

    if (t < 256) {
        float px = spos[t * 3 + 0], py = spos[t * 3 + 1], pz = spos[t * 3 + 2];
        float pn = px * px + py * py + pz * pz;
        float d[NKCLUST];
        int ord[NKCLUST];
        for (int k = 0; k < NKCLUST; k++) {
            float d2 = pn + fcn[k] - 2.0f * (px * fcx[k] + py * fcy[k] + pz * fcz[k]);
            d[k] = sqrtf(fmaxf(d2, 0.0f));
            ord[k] = k;
        }
        for (int a = 1; a < NKCLUST; a++) {
            int key = ord[a]; float kd = d[key];
            int bq = a - 1;
            while (bq >= 0 && d[ord[bq]] > kd) { ord[bq + 1] = ord[bq]; bq--; }
            ord[bq + 1] = key;
        }
        for (int k = 0; k < NKCLUST; k++) sord[t][k] = (unsigned char)ord[k];
    }
    __syncthreads();

    if (t == 0) {
        for (int rr = 0; rr < 256; rr++) {
            int chosen = sord[rr][0];
            for (int k = 0; k < NKCLUST; k++) {
                int cid = sord[rr][k];
                if (scounts[cid] < 16) { chosen = cid; break; }
            }
            scounts[chosen]++;
            out[rr] = (float)chosen;
        }
    }
}

// ---------------- launch ----------------
extern "C" void kernel_launch(void* const* d_in, const int* in_sizes, int n_in,
                              void* d_out, int out_size) {
    const float* features = nullptr;
    const float* pos = nullptr;
    for (int i = 0; i < n_in; i++) {
        if (in_sizes[i] == NB * NC * KDIM)   features = (const float*)d_in[i];
        else if (in_sizes[i] == NB * NC * 3) pos      = (const float*)d_in[i];
    }
    if (!features) features = (const float*)d_in[0];
    if (!pos)      pos      = (const float*)d_in[1];
    float* out = (float*)d_out;

    cudaFuncSetAttribute(gram_mma, cudaFuncAttributeMaxDynamicSharedMemorySize, SM_TOTAL);

    // slot-alignment: gram stays the 4th launch (ncu-profiled slot)
    dummy_kernel<<<1, 32>>>();
    dummy_kernel<<<1, 32>>>();
    convert_kernel<<<(NB * NC * KDIM) / (256 * 8), 256>>>(features);
    dim3 g1(7, SPLITS, NB);
    gram_mma<<<g1, GT, SM_TOTAL>>>(0);
    reduce_kernel<<<(NB * NC * NC) / 256, 256>>>();
    dim3 g2(9, 8);
    rowsum_kernel<<<g2, 256>>>(pos);
    fps_kernel<<<9, 256>>>(pos);
    tail_kernel<<<1, 512>>>(pos, out);
}

// round 14
// speedup vs baseline: 1.6273x; 1.6273x over previous
#include <cuda_runtime.h>
#include <cuda_bf16.h>
#include <cstdint>

#define KDIM 16384
#define NB 8
#define NC 256
#define NKCLUST 16
#define SPLITS 6
#define KC 64
#define TILEB 16384              // one 128x64 bf16 tile (128B rows)
#define BUFB  (4 * TILEB)        // Ahi,Alo,Bhi,Blo per stage
#define NSTAGE 3
#define SM_TOTAL (NSTAGE * BUFB) // 192KB dynamic smem
#define GT 512                   // 16 warps

// ---------------- scratch ----------------
__device__ __nv_bfloat16 g_hi[NB][NC][KDIM];
__device__ __nv_bfloat16 g_lo[NB][NC][KDIM];
__device__ float  g_part[SPLITS][NB][NC][NC];
__device__ float  g_G[NB][NC][NC];
__device__ double g_rowpart[9][8][NC];
__device__ int    g_sel[NB][NKCLUST];
__device__ int    g_selpos[NKCLUST];

__device__ __forceinline__ uint32_t smem_u32(const void* p) {
    uint32_t a;
    asm("{ .reg .u64 t; cvta.to.shared.u64 t, %1; cvt.u32.u64 %0, t; }" : "=r"(a) : "l"(p));
    return a;
}
__device__ __forceinline__ uint32_t sw128(uint32_t off) { return off ^ ((off >> 3) & 0x70); }

#define CP_ASYNC16(dst, src) \
    asm volatile("cp.async.cg.shared.global [%0], [%1], 16;" :: "r"(dst), "l"(src))
#define CP_COMMIT() asm volatile("cp.async.commit_group;" ::: "memory")
#define CP_WAIT(N)  asm volatile("cp.async.wait_group %0;" :: "n"(N) : "memory")

#define LDSM4(r, addr) \
    asm volatile("ldmatrix.sync.aligned.m8n8.x4.shared.b16 {%0,%1,%2,%3}, [%4];" \
                 : "=r"((r)[0]), "=r"((r)[1]), "=r"((r)[2]), "=r"((r)[3]) : "r"(addr))

__device__ __forceinline__ void mma16816(float* c, const uint32_t* a, const uint32_t* b) {
    asm volatile("mma.sync.aligned.m16n8k16.row.col.f32.bf16.bf16.f32 "
                 "{%0,%1,%2,%3}, {%4,%5,%6,%7}, {%8,%9}, {%0,%1,%2,%3};"
                 : "+f"(c[0]), "+f"(c[1]), "+f"(c[2]), "+f"(c[3])
                 : "r"(a[0]), "r"(a[1]), "r"(a[2]), "r"(a[3]), "r"(b[0]), "r"(b[1]));
}

// ---------------- Kernel D: dummy (ncu slot alignment) ----------------
__global__ void dummy_kernel() {}

// ---------------- Kernel 0: fp32 -> bf16 hi/lo split ----------------
__global__ void __launch_bounds__(256) convert_kernel(const float* __restrict__ A) {
    size_t gid = (size_t)blockIdx.x * 256 + threadIdx.x;
    size_t base = gid * 8;
    float4 v0 = *reinterpret_cast<const float4*>(A + base);
    float4 v1 = *reinterpret_cast<const float4*>(A + base + 4);
    __nv_bfloat162 h[4];
    h[0] = __float22bfloat162_rn(make_float2(v0.x, v0.y));
    h[1] = __float22bfloat162_rn(make_float2(v0.z, v0.w));
    h[2] = __float22bfloat162_rn(make_float2(v1.x, v1.y));
    h[3] = __float22bfloat162_rn(make_float2(v1.z, v1.w));
    float2 f0 = __bfloat1622float2(h[0]), f1 = __bfloat1622float2(h[1]);
    float2 f2 = __bfloat1622float2(h[2]), f3 = __bfloat1622float2(h[3]);
    __nv_bfloat162 l[4];
    l[0] = __float22bfloat162_rn(make_float2(v0.x - f0.x, v0.y - f0.y));
    l[1] = __float22bfloat162_rn(make_float2(v0.z - f1.x, v0.w - f1.y));
    l[2] = __float22bfloat162_rn(make_float2(v1.x - f2.x, v1.y - f2.y));
    l[3] = __float22bfloat162_rn(make_float2(v1.z - f3.x, v1.w - f3.y));
    *reinterpret_cast<uint4*>(&g_hi[0][0][0] + base) = *reinterpret_cast<uint4*>(h);
    *reinterpret_cast<uint4*>(&g_lo[0][0][0] + base) = *reinterpret_cast<uint4*>(l);
}

// ---------------- Kernel 1: bf16 mma.sync Gram (R11 config, 1 barrier) ----
// grid (3 tiles, SPLITS, NB), block 512. Warp grid 4x4, warp tile 32x32.
__global__ void __launch_bounds__(GT, 1) gram_mma(int unused) {
    extern __shared__ char smem[];
    uint32_t smb = smem_u32(smem);
    int tileId = blockIdx.x, s = blockIdx.y, b = blockIdx.z;
    int ti = (tileId == 2) ? 1 : 0;
    int tj = (tileId == 0) ? 0 : 1;
    bool diag = (ti == tj);

    const __nv_bfloat16* AhiR = &g_hi[b][ti * 128][0];
    const __nv_bfloat16* AloR = &g_lo[b][ti * 128][0];
    const __nv_bfloat16* BhiR = &g_hi[b][tj * 128][0];
    const __nv_bfloat16* BloR = &g_lo[b][tj * 128][0];

    int kb = ((s * KDIM) / SPLITS) & ~63;
    int ke = (((s + 1) * KDIM) / SPLITS) & ~63;
    if (s == SPLITS - 1) ke = KDIM;
    int n = (ke - kb) / KC;

    int t = threadIdx.x, l = t & 31, wid = t >> 5;
    int wr = wid >> 2, wc = wid & 3;        // 4x4 warp grid; warp tile 32x32

    int lrow = t >> 2;                      // 0..127, 4 threads per row
    int lseg = (t & 3) * 2;                 // 2 16B segs per thread per tile

    float acc[2][4][4];
#pragma unroll
    for (int f = 0; f < 2; f++)
#pragma unroll
        for (int g = 0; g < 4; g++)
#pragma unroll
            for (int q = 0; q < 4; q++) acc[f][g][q] = 0.0f;

    int mL = l & 15;
    int kaA = ((l >> 4) & 1) * 16;
    int nL = (l & 7) + ((l >> 4) & 1) * 8;
    int kaB = ((l >> 3) & 1) * 16;
    uint32_t arow[2], brow[2];
#pragma unroll
    for (int f = 0; f < 2; f++) arow[f] = (uint32_t)((wr * 32 + f * 16 + mL) * 128 + kaA);
#pragma unroll
    for (int g2 = 0; g2 < 2; g2++) brow[g2] = (uint32_t)((wc * 32 + g2 * 16 + nL) * 128 + kaB);

    auto load_chunk = [&](int c) {
        if (c < n) {
            int k0 = kb + c * KC;
            uint32_t base = smb + (uint32_t)(c % NSTAGE) * BUFB;
            const __nv_bfloat16* srcAh = AhiR + (size_t)lrow * KDIM + k0 + lseg * 8;
            const __nv_bfloat16* srcAl = AloR + (size_t)lrow * KDIM + k0 + lseg * 8;
            uint32_t doff0 = sw128((uint32_t)(lrow * 128 + lseg * 16));
            uint32_t doff1 = sw128((uint32_t)(lrow * 128 + (lseg + 1) * 16));
            CP_ASYNC16(base + doff0, srcAh);
            CP_ASYNC16(base + doff1, srcAh + 8);
            CP_ASYNC16(base + TILEB + doff0, srcAl);
            CP_ASYNC16(base + TILEB + doff1, srcAl + 8);
            if (!diag) {
                const __nv_bfloat16* srcBh = BhiR + (size_t)lrow * KDIM + k0 + lseg * 8;
                const __nv_bfloat16* srcBl = BloR + (size_t)lrow * KDIM + k0 + lseg * 8;
                CP_ASYNC16(base + 2 * TILEB + doff0, srcBh);
                CP_ASYNC16(base + 2 * TILEB + doff1, srcBh + 8);
                CP_ASYNC16(base + 3 * TILEB + doff0, srcBl);
                CP_ASYNC16(base + 3 * TILEB + doff1, srcBl + 8);
            }
        }
        CP_COMMIT();
    };

    load_chunk(0);
    load_chunk(1);

    for (int c = 0; c < n; c++) {
        CP_WAIT(1);
        __syncthreads();        // chunk c visible; all warps' mma(c-1) done
        load_chunk(c + 2);      // stage (c+2)%3 == (c-1)%3, safe now

        uint32_t base = smb + (uint32_t)(c % NSTAGE) * BUFB;
        uint32_t ahiB = base, aloB = base + TILEB;
        uint32_t bhiB = diag ? base : base + 2 * TILEB;
        uint32_t bloB = diag ? base + TILEB : base + 3 * TILEB;
#pragma unroll
        for (int kk = 0; kk < 4; kk++) {
            uint32_t ah[2][4], al[2][4], bh[2][4], bl[2][4];
#pragma unroll
            for (int f = 0; f < 2; f++) {
                uint32_t o = sw128(arow[f] + kk * 32);
                LDSM4(ah[f], ahiB + o);
                LDSM4(al[f], aloB + o);
            }
#pragma unroll
            for (int g2 = 0; g2 < 2; g2++) {
                uint32_t o = sw128(brow[g2] + kk * 32);
                LDSM4(bh[g2], bhiB + o);
                LDSM4(bl[g2], bloB + o);
            }
#pragma unroll
            for (int f = 0; f < 2; f++)
#pragma unroll
                for (int g = 0; g < 4; g++) {
                    const uint32_t* Bh = &bh[g >> 1][(g & 1) * 2];
                    const uint32_t* Bl = &bl[g >> 1][(g & 1) * 2];
                    mma16816(acc[f][g], ah[f], Bh);
                    mma16816(acc[f][g], ah[f], Bl);
                    mma16816(acc[f][g], al[f], Bh);
                }
        }
        // single-barrier mainloop: next iteration's top barrier orders reuse
    }

#pragma unroll
    for (int f = 0; f < 2; f++)
#pragma unroll
        for (int g = 0; g < 4; g++) {
            int m = wr * 32 + f * 16 + (l >> 2);
            int nn = wc * 32 + g * 8 + (l & 3) * 2;
            int gm = ti * 128 + m, gn = tj * 128 + nn;
            *reinterpret_cast<float2*>(&g_part[s][b][gm][gn]) =
                make_float2(acc[f][g][0], acc[f][g][1]);
            *reinterpret_cast<float2*>(&g_part[s][b][gm + 8][gn]) =
                make_float2(acc[f][g][2], acc[f][g][3]);
        }
}

// ---------------- Kernel 2: deterministic split reduction + mirror ---------
__global__ void __launch_bounds__(256) reduce_kernel() {
    int gid = blockIdx.x * 256 + threadIdx.x;
    int b  = gid >> 16;
    int ij = gid & 65535;
    int i  = ij >> 8;
    int j  = ij & 255;
    int si = i, sj = j;
    if (i >= 128 && j < 128) { si = j; sj = i; }
    float acc = 0.0f;
#pragma unroll
    for (int s = 0; s < SPLITS; s++) acc += g_part[s][b][si][sj];
    g_G[b][i][j] = acc;
}

// ---------------- Kernel 2b: parallel row sums ----------------
__global__ void __launch_bounds__(256) rowsum_kernel(const float* __restrict__ pos) {
    int mode = blockIdx.x;
    int part = blockIdx.y;
    int j = threadIdx.x;
    double acc = 0.0;
    if (mode == 0) {
        float px = pos[j * 3 + 0], py = pos[j * 3 + 1], pz = pos[j * 3 + 2];
        float pn = px * px + py * py + pz * pz;
        for (int i = part * 32; i < part * 32 + 32; i++) {
            float qx = pos[i * 3 + 0], qy = pos[i * 3 + 1], qz = pos[i * 3 + 2];
            float qn = qx * qx + qy * qy + qz * qz;
            float d2 = qn + pn - 2.0f * (qx * px + qy * py + qz * pz);
            acc += (double)sqrtf(fmaxf(d2, 0.0f));
        }
    } else {
        const float* Gb = &g_G[mode - 1][0][0];
        float nj = Gb[j * 256 + j];
        for (int i = part * 32; i < part * 32 + 32; i++) {
            float d2 = Gb[i * 256 + i] + nj - 2.0f * Gb[i * 256 + j];
            acc += (double)sqrtf(fmaxf(d2, 0.0f));
        }
    }
    g_rowpart[mode][part][j] = acc;
}

// ---------------- Kernel 3: farthest point sampling ----------------
__global__ void __launch_bounds__(256) fps_kernel(const float* __restrict__ pos) {
    int j = threadIdx.x;
    int mode = blockIdx.x;
    __shared__ double sdv[256];
    __shared__ int    sidx[256];
    __shared__ float  spx[256], spy[256], spz[256], snrm[256];
    __shared__ int    ssel[NKCLUST];

    const float* Gb = nullptr;
    if (mode == 0) {
        spx[j] = pos[j * 3 + 0]; spy[j] = pos[j * 3 + 1]; spz[j] = pos[j * 3 + 2];
    } else {
        Gb = &g_G[mode - 1][0][0];
    }
    __syncthreads();
    if (mode == 0) snrm[j] = spx[j] * spx[j] + spy[j] * spy[j] + spz[j] * spz[j];
    else           snrm[j] = Gb[j * 256 + j];
    __syncthreads();

    auto dist = [&](int i) -> float {
        float d2;
        if (mode == 0) {
            float dot = spx[i] * spx[j] + spy[i] * spy[j] + spz[i] * spz[j];
            d2 = snrm[i] + snrm[j] - 2.0f * dot;
        } else {
            d2 = snrm[i] + snrm[j] - 2.0f * Gb[i * 256 + j];
        }
        return sqrtf(fmaxf(d2, 0.0f));
    };

    double rs = 0.0;
#pragma unroll
    for (int p = 0; p < 8; p++) rs += g_rowpart[mode][p][j];
    sdv[j] = rs; sidx[j] = j;
    __syncthreads();
    for (int off = 128; off > 0; off >>= 1) {
        if (j < off) {
            double v2 = sdv[j + off]; int i2 = sidx[j + off];
            if (v2 > sdv[j] || (v2 == sdv[j] && i2 < sidx[j])) { sdv[j] = v2; sidx[j] = i2; }
        }
        __syncthreads();
    }
    int cur = sidx[0];
    __syncthreads();
    if (j == 0) ssel[0] = cur;
    float mind = dist(cur);

    for (int it = 1; it < NKCLUST; it++) {
        sdv[j] = (double)mind; sidx[j] = j;
        __syncthreads();
        for (int off = 128; off > 0; off >>= 1) {
            if (j < off) {
                double v2 = sdv[j + off]; int i2 = sidx[j + off];
                if (v2 > sdv[j] || (v2 == sdv[j] && i2 < sidx[j])) { sdv[j] = v2; sidx[j] = i2; }
            }
            __syncthreads();
        }
        cur = sidx[0];
        __syncthreads();
        if (j == 0) ssel[it] = cur;
        mind = fminf(mind, dist(cur));
    }
    __syncthreads();
    if (j < NKCLUST) {
        if (mode == 0) g_selpos[j] = ssel[j];
        else           g_sel[mode - 1][j] = ssel[j];
    }
}

// ---------------- Kernel 4: fused assign + update + final ----------------
__global__ void __launch_bounds__(512) tail_kernel(const float* __restrict__ pos,
                                                   float* __restrict__ out) {
    __shared__ float spos[NB * NC * 3];
    __shared__ float scx[NB][NKCLUST], scy[NB][NKCLUST], scz[NB][NKCLUST], scn[NB][NKCLUST];
    __shared__ int   sta[NB * NC];
    __shared__ float ax[NKCLUST], ay[NKCLUST], az[NKCLUST], an[NKCLUST];
    __shared__ float fcx[NKCLUST], fcy[NKCLUST], fcz[NKCLUST], fcn[NKCLUST];
    __shared__ unsigned char sord[256][NKCLUST];
    __shared__ int scounts[NKCLUST];

    int t = threadIdx.x;
    for (int i = t; i < NB * NC * 3; i += 512) spos[i] = pos[i];
    if (t < NKCLUST) scounts[t] = 0;
    __syncthreads();

    if (t < NB * NKCLUST) {
        int b = t >> 4, k = t & 15;
        int si = g_sel[b][k];
        float x = spos[(b * 256 + si) * 3 + 0];
        float y = spos[(b * 256 + si) * 3 + 1];
        float z = spos[(b * 256 + si) * 3 + 2];
        scx[b][k] = x; scy[b][k] = y; scz[b][k] = z; scn[b][k] = x * x + y * y + z * z;
    }
    __syncthreads();

    for (int p = t; p < NB * NC; p += 512) {
        int b = p >> 8;
        float px = spos[p * 3 + 0], py = spos[p * 3 + 1], pz = spos[p * 3 + 2];
        float pn = px * px + py * py + pz * pz;
        float best = 1e30f; int bi = 0;
        for (int k = 0; k < NKCLUST; k++) {
            float d2 = pn + scn[b][k] - 2.0f * (px * scx[b][k] + py * scy[b][k] + pz * scz[b][k]);
            float d = sqrtf(fmaxf(d2, 0.0f));
            if (d < best) { best = d; bi = k; }
        }
        sta[p] = bi;
    }
    __syncthreads();

    int wid = t >> 5, l = t & 31;
    if (wid < NKCLUST) {
        float sx = 0.f, sy = 0.f, sz = 0.f, cnt = 0.f;
        for (int p = l; p < NB * NC; p += 32) {
            if (sta[p] == wid) {
                sx += spos[p * 3 + 0]; sy += spos[p * 3 + 1]; sz += spos[p * 3 + 2];
                cnt += 1.0f;
            }
        }
#pragma unroll
        for (int off = 16; off > 0; off >>= 1) {
            sx  += __shfl_down_sync(0xffffffffu, sx,  off);
            sy  += __shfl_down_sync(0xffffffffu, sy,  off);
            sz  += __shfl_down_sync(0xffffffffu, sz,  off);
            cnt += __shfl_down_sync(0xffffffffu, cnt, off);
        }
        if (l == 0) {
            if (cnt > 0.f) {
                float dn = fmaxf(cnt, 1.0f);
                ax[wid] = sx / dn; ay[wid] = sy / dn; az[wid] = sz / dn;
            } else { ax[wid] = 0.f; ay[wid] = 0.f; az[wid] = 0.f; }
            an[wid] = ax[wid] * ax[wid] + ay[wid] * ay[wid] + az[wid] * az[wid];
        }
    }
    __syncthreads();

    if (t < NKCLUST) {
        int si = g_selpos[t];
        float cx = spos[si * 3 + 0], cy = spos[si * 3 + 1], cz = spos[si * 3 + 2];
        float cnrm = cx * cx + cy * cy + cz * cz;
        float best = 1e30f; int bm = 0;
        for (int m = 0; m < NKCLUST; m++) {
            float d2 = cnrm + an[m] - 2.0f * (cx * ax[m] + cy * ay[m] + cz * az[m]);
            float d = sqrtf(fmaxf(d2, 0.0f));
            if (d < best) { best = d; bm = m; }
        }
        float nx = 0.8f * cx + 0.2f * ax[bm];
        float ny = 0.8f * cy + 0.2f * ay[bm];
        float nz = 0.8f * cz + 0.2f * az[bm];
        fcx[t] = nx; fcy[t] = ny; fcz[t] = nz; fcn[t] = nx * nx + ny * ny + nz * nz;
    }
    __syncthreads();

    if (t < 256) {
        float px = spos[t * 3 + 0], py = spos[t * 3 + 1], pz = spos[t * 3 + 2];
        float pn = px * px + py * py + pz * pz;
        float d[NKCLUST];
        int ord[NKCLUST];
        for (int k = 0; k < NKCLUST; k++) {
            float d2 = pn + fcn[k] - 2.0f * (px * fcx[k] + py * fcy[k] + pz * fcz[k]);
            d[k] = sqrtf(fmaxf(d2, 0.0f));
            ord[k] = k;
        }
        for (int a = 1; a < NKCLUST; a++) {
            int key = ord[a]; float kd = d[key];
            int bq = a - 1;
            while (bq >= 0 && d[ord[bq]] > kd) { ord[bq + 1] = ord[bq]; bq--; }
            ord[bq + 1] = key;
        }
        for (int k = 0; k < NKCLUST; k++) sord[t][k] = (unsigned char)ord[k];
    }
    __syncthreads();

    if (t == 0) {
        for (int rr = 0; rr < 256; rr++) {
            int chosen = sord[rr][0];
            for (int k = 0; k < NKCLUST; k++) {
                int cid = sord[rr][k];
                if (scounts[cid] < 16) { chosen = cid; break; }
            }
            scounts[chosen]++;
            out[rr] = (float)chosen;
        }
    }
}

// ---------------- launch ----------------
extern "C" void kernel_launch(void* const* d_in, const int* in_sizes, int n_in,
                              void* d_out, int out_size) {
    const float* features = nullptr;
    const float* pos = nullptr;
    for (int i = 0; i < n_in; i++) {
        if (in_sizes[i] == NB * NC * KDIM)   features = (const float*)d_in[i];
        else if (in_sizes[i] == NB * NC * 3) pos      = (const float*)d_in[i];
    }
    if (!features) features = (const float*)d_in[0];
    if (!pos)      pos      = (const float*)d_in[1];
    float* out = (float*)d_out;

    cudaFuncSetAttribute(gram_mma, cudaFuncAttributeMaxDynamicSharedMemorySize, SM_TOTAL);

    // slot-alignment: gram stays the 4th launch (ncu-profiled slot)
    dummy_kernel<<<1, 32>>>();
    dummy_kernel<<<1, 32>>>();
    convert_kernel<<<(NB * NC * KDIM) / (256 * 8), 256>>>(features);
    dim3 g1(3, SPLITS, NB);
    gram_mma<<<g1, GT, SM_TOTAL>>>(0);
    reduce_kernel<<<(NB * NC * NC) / 256, 256>>>();
    dim3 g2(9, 8);
    rowsum_kernel<<<g2, 256>>>(pos);
    fps_kernel<<<9, 256>>>(pos);
    tail_kernel<<<1, 512>>>(pos, out);
}

// round 15
// speedup vs baseline: 1.8157x; 1.1158x over previous
#include <cuda_runtime.h>
#include <cstdint>

#define KDIM 16384
#define NB 8
#define NC 256
#define NKCLUST 16
#define SPLITS 6
#define KC 64
#define TILE32 32768             // one 128x64 fp32 tile (256B rows)
#define STGB  (2 * TILE32)       // X,Y per stage = 64KB
#define NSTAGE 3
#define SM_TOTAL (NSTAGE * STGB) // 192KB
#define GT 512

// ---------------- scratch ----------------
__device__ float  g_part[SPLITS][NB][NC][NC];
__device__ float  g_G[NB][NC][NC];
__device__ double g_rowpart[9][8][NC];
__device__ int    g_sel[NB][NKCLUST];
__device__ int    g_selpos[NKCLUST];

__device__ __forceinline__ uint32_t smem_u32(const void* p) {
    uint32_t a;
    asm("{ .reg .u64 t; cvta.to.shared.u64 t, %1; cvt.u32.u64 %0, t; }" : "=r"(a) : "l"(p));
    return a;
}
// swizzle for 256B rows: 16B-granule column ^= (row & 7)
__device__ __forceinline__ uint32_t sw256(uint32_t off) { return off ^ ((off >> 4) & 0x70); }

#define CP_ASYNC16(dst, src) \
    asm volatile("cp.async.cg.shared.global [%0], [%1], 16;" :: "r"(dst), "l"(src))
#define CP_COMMIT() asm volatile("cp.async.commit_group;" ::: "memory")
#define CP_WAIT(N)  asm volatile("cp.async.wait_group %0;" :: "n"(N) : "memory")

#define LDSM4(r, addr) \
    asm volatile("ldmatrix.sync.aligned.m8n8.x4.shared.b16 {%0,%1,%2,%3}, [%4];" \
                 : "=r"((r)[0]), "=r"((r)[1]), "=r"((r)[2]), "=r"((r)[3]) : "r"(addr))

__device__ __forceinline__ void mma_tf32(float* c, const uint32_t* a, const uint32_t* b) {
    asm volatile("mma.sync.aligned.m16n8k8.row.col.f32.tf32.tf32.f32 "
                 "{%0,%1,%2,%3}, {%4,%5,%6,%7}, {%8,%9}, {%0,%1,%2,%3};"
                 : "+f"(c[0]), "+f"(c[1]), "+f"(c[2]), "+f"(c[3])
                 : "r"(a[0]), "r"(a[1]), "r"(a[2]), "r"(a[3]), "r"(b[0]), "r"(b[1]));
}

// ---------------- Kernel D: dummy (ncu slot alignment) ----------------
__global__ void dummy_kernel() {}

// ---------------- Kernel 1: tf32 mma.sync Gram, direct fp32 loads ---------
// grid (3 tiles, SPLITS, NB), block 512. Warp grid 4x4, warp tile 32x32.
__global__ void __launch_bounds__(GT, 1) gram_mma(const float* __restrict__ A) {
    extern __shared__ char smem[];
    uint32_t smb = smem_u32(smem);
    int tileId = blockIdx.x, s = blockIdx.y, b = blockIdx.z;
    int ti = (tileId == 2) ? 1 : 0;
    int tj = (tileId == 0) ? 0 : 1;
    bool diag = (ti == tj);

    const float* Xr = A + ((size_t)b * NC + ti * 128) * KDIM;
    const float* Yr = A + ((size_t)b * NC + tj * 128) * KDIM;

    int kb = ((s * KDIM) / SPLITS) & ~63;
    int ke = (((s + 1) * KDIM) / SPLITS) & ~63;
    if (s == SPLITS - 1) ke = KDIM;
    int n = (ke - kb) / KC;

    int t = threadIdx.x, l = t & 31, wid = t >> 5;
    int wr = wid >> 2, wc = wid & 3;        // 4x4 warp grid; warp tile 32x32

    int lrow = t >> 2;                      // 0..127, 4 threads per row
    int lc4  = (t & 3) * 4;                 // 4 consecutive 16B chunks per thread

    float acc[2][4][4];
#pragma unroll
    for (int f = 0; f < 2; f++)
#pragma unroll
        for (int g = 0; g < 4; g++)
#pragma unroll
            for (int q = 0; q < 4; q++) acc[f][g][q] = 0.0f;

    // ldmatrix lane bases.
    // A (x4 per 16-row group, one k8 step): M0 rows 0-7 c0-3, M1 rows 8-15 c0-3,
    //   M2 rows 0-7 c4-7, M3 rows 8-15 c4-7 (f32 cols).
    int r_l  = (l & 7) + ((l >> 3) & 1) * 8;
    int acol = ((l >> 4) & 1) * 16;         // +16B for matrices 2,3
    uint32_t arowb[2];
#pragma unroll
    for (int f = 0; f < 2; f++)
        arowb[f] = (uint32_t)((wr * 32 + f * 16 + r_l) * 256 + acol);
    // B (x4 per n8 group covering 2 k8 steps): M0..M3 same n rows, colbytes +0,16,32,48
    uint32_t browb[4];
#pragma unroll
    for (int g = 0; g < 4; g++)
        browb[g] = (uint32_t)((wc * 32 + g * 8 + (l & 7)) * 256 + (l >> 3) * 16);

    auto load_chunk = [&](int c) {
        if (c < n) {
            int k0 = kb + c * KC;
            uint32_t base = smb + (uint32_t)(c % NSTAGE) * STGB;
            const float* srcX = Xr + (size_t)lrow * KDIM + k0 + lc4 * 4;
#pragma unroll
            for (int i = 0; i < 4; i++) {
                uint32_t d = sw256((uint32_t)(lrow * 256 + (lc4 + i) * 16));
                CP_ASYNC16(base + d, srcX + i * 4);
            }
            if (!diag) {
                const float* srcY = Yr + (size_t)lrow * KDIM + k0 + lc4 * 4;
#pragma unroll
                for (int i = 0; i < 4; i++) {
                    uint32_t d = sw256((uint32_t)(lrow * 256 + (lc4 + i) * 16));
                    CP_ASYNC16(base + TILE32 + d, srcY + i * 4);
                }
            }
        }
        CP_COMMIT();
    };

    load_chunk(0);
    load_chunk(1);

    for (int c = 0; c < n; c++) {
        CP_WAIT(1);
        __syncthreads();        // chunk c visible; all warps' mma(c-1) done
        load_chunk(c + 2);      // stage (c+2)%3 == (c-1)%3, safe now

        uint32_t base = smb + (uint32_t)(c % NSTAGE) * STGB;
        uint32_t Xb = base;
        uint32_t Yb = diag ? base : base + TILE32;
#pragma unroll
        for (int kk2 = 0; kk2 < 4; kk2++) {
            uint32_t bb[4][4];
#pragma unroll
            for (int g = 0; g < 4; g++)
                LDSM4(bb[g], Yb + sw256(browb[g] + kk2 * 64));
#pragma unroll
            for (int sub = 0; sub < 2; sub++) {
                int k = kk2 * 2 + sub;
                uint32_t aa[2][4];
#pragma unroll
                for (int f = 0; f < 2; f++)
                    LDSM4(aa[f], Xb + sw256(arowb[f] + k * 32));
#pragma unroll
                for (int f = 0; f < 2; f++)
#pragma unroll
                    for (int g = 0; g < 4; g++)
                        mma_tf32(acc[f][g], aa[f], &bb[g][sub * 2]);
            }
        }
        // single-barrier mainloop
    }

#pragma unroll
    for (int f = 0; f < 2; f++)
#pragma unroll
        for (int g = 0; g < 4; g++) {
            int m = wr * 32 + f * 16 + (l >> 2);
            int nn = wc * 32 + g * 8 + (l & 3) * 2;
            int gm = ti * 128 + m, gn = tj * 128 + nn;
            *reinterpret_cast<float2*>(&g_part[s][b][gm][gn]) =
                make_float2(acc[f][g][0], acc[f][g][1]);
            *reinterpret_cast<float2*>(&g_part[s][b][gm + 8][gn]) =
                make_float2(acc[f][g][2], acc[f][g][3]);
        }
}

// ---------------- Kernel 2: deterministic split reduction + mirror ---------
__global__ void __launch_bounds__(256) reduce_kernel() {
    int gid = blockIdx.x * 256 + threadIdx.x;
    int b  = gid >> 16;
    int ij = gid & 65535;
    int i  = ij >> 8;
    int j  = ij & 255;
    int si = i, sj = j;
    if (i >= 128 && j < 128) { si = j; sj = i; }
    float acc = 0.0f;
#pragma unroll
    for (int s = 0; s < SPLITS; s++) acc += g_part[s][b][si][sj];
    g_G[b][i][j] = acc;
}

// ---------------- Kernel 2b: parallel row sums ----------------
__global__ void __launch_bounds__(256) rowsum_kernel(const float* __restrict__ pos) {
    int mode = blockIdx.x;
    int part = blockIdx.y;
    int j = threadIdx.x;
    double acc = 0.0;
    if (mode == 0) {
        float px = pos[j * 3 + 0], py = pos[j * 3 + 1], pz = pos[j * 3 + 2];
        float pn = px * px + py * py + pz * pz;
        for (int i = part * 32; i < part * 32 + 32; i++) {
            float qx = pos[i * 3 + 0], qy = pos[i * 3 + 1], qz = pos[i * 3 + 2];
            float qn = qx * qx + qy * qy + qz * qz;
            float d2 = qn + pn - 2.0f * (qx * px + qy * py + qz * pz);
            acc += (double)sqrtf(fmaxf(d2, 0.0f));
        }
    } else {
        const float* Gb = &g_G[mode - 1][0][0];
        float nj = Gb[j * 256 + j];
        for (int i = part * 32; i < part * 32 + 32; i++) {
            float d2 = Gb[i * 256 + i] + nj - 2.0f * Gb[i * 256 + j];
            acc += (double)sqrtf(fmaxf(d2, 0.0f));
        }
    }
    g_rowpart[mode][part][j] = acc;
}

// ---------------- Kernel 3: farthest point sampling ----------------
__global__ void __launch_bounds__(256) fps_kernel(const float* __restrict__ pos) {
    int j = threadIdx.x;
    int mode = blockIdx.x;
    __shared__ double sdv[256];
    __shared__ int    sidx[256];
    __shared__ float  spx[256], spy[256], spz[256], snrm[256];
    __shared__ int    ssel[NKCLUST];

    const float* Gb = nullptr;
    if (mode == 0) {
        spx[j] = pos[j * 3 + 0]; spy[j] = pos[j * 3 + 1]; spz[j] = pos[j * 3 + 2];
    } else {
        Gb = &g_G[mode - 1][0][0];
    }
    __syncthreads();
    if (mode == 0) snrm[j] = spx[j] * spx[j] + spy[j] * spy[j] + spz[j] * spz[j];
    else           snrm[j] = Gb[j * 256 + j];
    __syncthreads();

    auto dist = [&](int i) -> float {
        float d2;
        if (mode == 0) {
            float dot = spx[i] * spx[j] + spy[i] * spy[j] + spz[i] * spz[j];
            d2 = snrm[i] + snrm[j] - 2.0f * dot;
        } else {
            d2 = snrm[i] + snrm[j] - 2.0f * Gb[i * 256 + j];
        }
        return sqrtf(fmaxf(d2, 0.0f));
    };

    double rs = 0.0;
#pragma unroll
    for (int p = 0; p < 8; p++) rs += g_rowpart[mode][p][j];
    sdv[j] = rs; sidx[j] = j;
    __syncthreads();
    for (int off = 128; off > 0; off >>= 1) {
        if (j < off) {
            double v2 = sdv[j + off]; int i2 = sidx[j + off];
            if (v2 > sdv[j] || (v2 == sdv[j] && i2 < sidx[j])) { sdv[j] = v2; sidx[j] = i2; }
        }
        __syncthreads();
    }
    int cur = sidx[0];
    __syncthreads();
    if (j == 0) ssel[0] = cur;
    float mind = dist(cur);

    for (int it = 1; it < NKCLUST; it++) {
        sdv[j] = (double)mind; sidx[j] = j;
        __syncthreads();
        for (int off = 128; off > 0; off >>= 1) {
            if (j < off) {
                double v2 = sdv[j + off]; int i2 = sidx[j + off];
                if (v2 > sdv[j] || (v2 == sdv[j] && i2 < sidx[j])) { sdv[j] = v2; sidx[j] = i2; }
            }
            __syncthreads();
        }
        cur = sidx[0];
        __syncthreads();
        if (j == 0) ssel[it] = cur;
        mind = fminf(mind, dist(cur));
    }
    __syncthreads();
    if (j < NKCLUST) {
        if (mode == 0) g_selpos[j] = ssel[j];
        else           g_sel[mode - 1][j] = ssel[j];
    }
}

// ---------------- Kernel 4: fused assign + update + final ----------------
__global__ void __launch_bounds__(512) tail_kernel(const float* __restrict__ pos,
                                                   float* __restrict__ out) {
    __shared__ float spos[NB * NC * 3];
    __shared__ float scx[NB][NKCLUST], scy[NB][NKCLUST], scz[NB][NKCLUST], scn[NB][NKCLUST];
    __shared__ int   sta[NB * NC];
    __shared__ float ax[NKCLUST], ay[NKCLUST], az[NKCLUST], an[NKCLUST];
    __shared__ float fcx[NKCLUST], fcy[NKCLUST], fcz[NKCLUST], fcn[NKCLUST];
    __shared__ unsigned char sord[256][NKCLUST];
    __shared__ int scounts[NKCLUST];

    int t = threadIdx.x;
    for (int i = t; i < NB * NC * 3; i += 512) spos[i] = pos[i];
    if (t < NKCLUST) scounts[t] = 0;
    __syncthreads();

    if (t < NB * NKCLUST) {
        int b = t >> 4, k = t & 15;
        int si = g_sel[b][k];
        float x = spos[(b * 256 + si) * 3 + 0];
        float y = spos[(b * 256 + si) * 3 + 1];
        float z = spos[(b * 256 + si) * 3 + 2];
        scx[b][k] = x; scy[b][k] = y; scz[b][k] = z; scn[b][k] = x * x + y * y + z * z;
    }
    __syncthreads();

    for (int p = t; p < NB * NC; p += 512) {
        int b = p >> 8;
        float px = spos[p * 3 + 0], py = spos[p * 3 + 1], pz = spos[p * 3 + 2];
        float pn = px * px + py * py + pz * pz;
        float best = 1e30f; int bi = 0;
        for (int k = 0; k < NKCLUST; k++) {
            float d2 = pn + scn[b][k] - 2.0f * (px * scx[b][k] + py * scy[b][k] + pz * scz[b][k]);
            float d = sqrtf(fmaxf(d2, 0.0f));
            if (d < best) { best = d; bi = k; }
        }
        sta[p] = bi;
    }
    __syncthreads();

    int wid = t >> 5, l = t & 31;
    if (wid < NKCLUST) {
        float sx = 0.f, sy = 0.f, sz = 0.f, cnt = 0.f;
        for (int p = l; p < NB * NC; p += 32) {
            if (sta[p] == wid) {
                sx += spos[p * 3 + 0]; sy += spos[p * 3 + 1]; sz += spos[p * 3 + 2];
                cnt += 1.0f;
            }
        }
#pragma unroll
        for (int off = 16; off > 0; off >>= 1) {
            sx  += __shfl_down_sync(0xffffffffu, sx,  off);
            sy  += __shfl_down_sync(0xffffffffu, sy,  off);
            sz  += __shfl_down_sync(0xffffffffu, sz,  off);
            cnt += __shfl_down_sync(0xffffffffu, cnt, off);
        }
        if (l == 0) {
            if (cnt > 0.f) {
                float dn = fmaxf(cnt, 1.0f);
                ax[wid] = sx / dn; ay[wid] = sy / dn; az[wid] = sz / dn;
            } else { ax[wid] = 0.f; ay[wid] = 0.f; az[wid] = 0.f; }
            an[wid] = ax[wid] * ax[wid] + ay[wid] * ay[wid] + az[wid] * az[wid];
        }
    }
    __syncthreads();

    if (t < NKCLUST) {
        int si = g_selpos[t];
        float cx = spos[si * 3 + 0], cy = spos[si * 3 + 1], cz = spos[si * 3 + 2];
        float cnrm = cx * cx + cy * cy + cz * cz;
        float best = 1e30f; int bm = 0;
        for (int m = 0; m < NKCLUST; m++) {
            float d2 = cnrm + an[m] - 2.0f * (cx * ax[m] + cy * ay[m] + cz * az[m]);
            float d = sqrtf(fmaxf(d2, 0.0f));
            if (d < best) { best = d; bm = m; }
        }
        float nx = 0.8f * cx + 0.2f * ax[bm];
        float ny = 0.8f * cy + 0.2f * ay[bm];
        float nz = 0.8f * cz + 0.2f * az[bm];
        fcx[t] = nx; fcy[t] = ny; fcz[t] = nz; fcn[t] = nx * nx + ny * ny + nz * nz;
    }
    __syncthreads();

    if (t < 256) {
        float px = spos[t * 3 + 0], py = spos[t * 3 + 1], pz = spos[t * 3 + 2];
        float pn = px * px + py * py + pz * pz;
        float d[NKCLUST];
        int ord[NKCLUST];
        for (int k = 0; k < NKCLUST; k++) {
            float d2 = pn + fcn[k] - 2.0f * (px * fcx[k] + py * fcy[k] + pz * fcz[k]);
            d[k] = sqrtf(fmaxf(d2, 0.0f));
            ord[k] = k;
        }
        for (int a = 1; a < NKCLUST; a++) {
            int key = ord[a]; float kd = d[key];
            int bq = a - 1;
            while (bq >= 0 && d[ord[bq]] > kd) { ord[bq + 1] = ord[bq]; bq--; }
            ord[bq + 1] = key;
        }
        for (int k = 0; k < NKCLUST; k++) sord[t][k] = (unsigned char)ord[k];
    }
    __syncthreads();

    if (t == 0) {
        for (int rr = 0; rr < 256; rr++) {
            int chosen = sord[rr][0];
            for (int k = 0; k < NKCLUST; k++) {
                int cid = sord[rr][k];
                if (scounts[cid] < 16) { chosen = cid; break; }
            }
            scounts[chosen]++;
            out[rr] = (float)chosen;
        }
    }
}

// ---------------- launch ----------------
extern "C" void kernel_launch(void* const* d_in, const int* in_sizes, int n_in,
                              void* d_out, int out_size) {
    const float* features = nullptr;
    const float* pos = nullptr;
    for (int i = 0; i < n_in; i++) {
        if (in_sizes[i] == NB * NC * KDIM)   features = (const float*)d_in[i];
        else if (in_sizes[i] == NB * NC * 3) pos      = (const float*)d_in[i];
    }
    if (!features) features = (const float*)d_in[0];
    if (!pos)      pos      = (const float*)d_in[1];
    float* out = (float*)d_out;

    cudaFuncSetAttribute(gram_mma, cudaFuncAttributeMaxDynamicSharedMemorySize, SM_TOTAL);

    // slot-alignment: gram stays the 4th launch (ncu-profiled slot)
    dummy_kernel<<<1, 32>>>();
    dummy_kernel<<<1, 32>>>();
    dummy_kernel<<<1, 32>>>();
    dim3 g1(3, SPLITS, NB);
    gram_mma<<<g1, GT, SM_TOTAL>>>(features);
    reduce_kernel<<<(NB * NC * NC) / 256, 256>>>();
    dim3 g2(9, 8);
    rowsum_kernel<<<g2, 256>>>(pos);
    fps_kernel<<<9, 256>>>(pos);
    tail_kernel<<<1, 512>>>(pos, out);
}

// round 16
// speedup vs baseline: 1.8737x; 1.0320x over previous
#include <cuda_runtime.h>
#include <cstdint>

#define KDIM 16384
#define NB 8
#define NC 256
#define NKCLUST 16
#define SPLITS 6
#define KC 64
#define TILE32 32768             // one 128x64 fp32 tile (256B rows)
#define STGB  (2 * TILE32)       // X,Y per stage = 64KB
#define NSTAGE 3
#define SM_TOTAL (NSTAGE * STGB) // 192KB
#define GT 512

// ---------------- scratch ----------------
__device__ float  g_part[SPLITS][NB][NC][NC];
__device__ float  g_G[NB][NC][NC];
__device__ double g_rowpart[9][8][NC];
__device__ int    g_sel[NB][NKCLUST];
__device__ int    g_selpos[NKCLUST];

__device__ __forceinline__ uint32_t smem_u32(const void* p) {
    uint32_t a;
    asm("{ .reg .u64 t; cvta.to.shared.u64 t, %1; cvt.u32.u64 %0, t; }" : "=r"(a) : "l"(p));
    return a;
}
// swizzle for 256B rows: 16B-granule column ^= (row & 7)
__device__ __forceinline__ uint32_t sw256(uint32_t off) { return off ^ ((off >> 4) & 0x70); }

#define CP_ASYNC16(dst, src) \
    asm volatile("cp.async.cg.shared.global [%0], [%1], 16;" :: "r"(dst), "l"(src))
#define CP_COMMIT() asm volatile("cp.async.commit_group;" ::: "memory")
#define CP_WAIT(N)  asm volatile("cp.async.wait_group %0;" :: "n"(N) : "memory")

#define LDSM4(r, addr) \
    asm volatile("ldmatrix.sync.aligned.m8n8.x4.shared.b16 {%0,%1,%2,%3}, [%4];" \
                 : "=r"((r)[0]), "=r"((r)[1]), "=r"((r)[2]), "=r"((r)[3]) : "r"(addr))

__device__ __forceinline__ void mma_tf32(float* c, const uint32_t* a, const uint32_t* b) {
    asm volatile("mma.sync.aligned.m16n8k8.row.col.f32.tf32.tf32.f32 "
                 "{%0,%1,%2,%3}, {%4,%5,%6,%7}, {%8,%9}, {%0,%1,%2,%3};"
                 : "+f"(c[0]), "+f"(c[1]), "+f"(c[2]), "+f"(c[3])
                 : "r"(a[0]), "r"(a[1]), "r"(a[2]), "r"(a[3]), "r"(b[0]), "r"(b[1]));
}

// ---------------- Kernel D: dummy (ncu slot alignment) ----------------
__global__ void dummy_kernel() {}

// ---------------- Kernel 1: tf32 mma.sync Gram, warp-staggered k-order ----
// grid (3 tiles, SPLITS, NB), block 512. Warp grid 4x4, warp tile 32x32.
__global__ void __launch_bounds__(GT, 1) gram_mma(const float* __restrict__ A) {
    extern __shared__ char smem[];
    uint32_t smb = smem_u32(smem);
    int tileId = blockIdx.x, s = blockIdx.y, b = blockIdx.z;
    int ti = (tileId == 2) ? 1 : 0;
    int tj = (tileId == 0) ? 0 : 1;
    bool diag = (ti == tj);

    const float* Xr = A + ((size_t)b * NC + ti * 128) * KDIM;
    const float* Yr = A + ((size_t)b * NC + tj * 128) * KDIM;

    int kb = ((s * KDIM) / SPLITS) & ~63;
    int ke = (((s + 1) * KDIM) / SPLITS) & ~63;
    if (s == SPLITS - 1) ke = KDIM;
    int n = (ke - kb) / KC;

    int t = threadIdx.x, l = t & 31, wid = t >> 5;
    int wr = wid >> 2, wc = wid & 3;        // 4x4 warp grid; warp tile 32x32
    int kst = wid & 3;                      // per-warp kk2 rotation (de-convoy)

    int lrow = t >> 2;                      // 0..127, 4 threads per row
    int lc4  = (t & 3) * 4;                 // 4 consecutive 16B chunks per thread

    float acc[2][4][4];
#pragma unroll
    for (int f = 0; f < 2; f++)
#pragma unroll
        for (int g = 0; g < 4; g++)
#pragma unroll
            for (int q = 0; q < 4; q++) acc[f][g][q] = 0.0f;

    int r_l  = (l & 7) + ((l >> 3) & 1) * 8;
    int acol = ((l >> 4) & 1) * 16;
    uint32_t arowb[2];
#pragma unroll
    for (int f = 0; f < 2; f++)
        arowb[f] = (uint32_t)((wr * 32 + f * 16 + r_l) * 256 + acol);
    uint32_t browb[4];
#pragma unroll
    for (int g = 0; g < 4; g++)
        browb[g] = (uint32_t)((wc * 32 + g * 8 + (l & 7)) * 256 + (l >> 3) * 16);

    auto load_chunk = [&](int c) {
        if (c < n) {
            int k0 = kb + c * KC;
            uint32_t base = smb + (uint32_t)(c % NSTAGE) * STGB;
            const float* srcX = Xr + (size_t)lrow * KDIM + k0 + lc4 * 4;
#pragma unroll
            for (int i = 0; i < 4; i++) {
                uint32_t d = sw256((uint32_t)(lrow * 256 + (lc4 + i) * 16));
                CP_ASYNC16(base + d, srcX + i * 4);
            }
            if (!diag) {
                const float* srcY = Yr + (size_t)lrow * KDIM + k0 + lc4 * 4;
#pragma unroll
                for (int i = 0; i < 4; i++) {
                    uint32_t d = sw256((uint32_t)(lrow * 256 + (lc4 + i) * 16));
                    CP_ASYNC16(base + TILE32 + d, srcY + i * 4);
                }
            }
        }
        CP_COMMIT();
    };

    load_chunk(0);
    load_chunk(1);

    for (int c = 0; c < n; c++) {
        CP_WAIT(1);
        __syncthreads();        // chunk c visible; all warps' mma(c-1) done
        load_chunk(c + 2);      // stage (c+2)%3 == (c-1)%3, safe now

        uint32_t base = smb + (uint32_t)(c % NSTAGE) * STGB;
        uint32_t Xb = base;
        uint32_t Yb = diag ? base : base + TILE32;
#pragma unroll
        for (int kk2i = 0; kk2i < 4; kk2i++) {
            int kk2 = (kk2i + kst) & 3;     // warp-staggered order
            uint32_t bb[4][4];
#pragma unroll
            for (int g = 0; g < 4; g++)
                LDSM4(bb[g], Yb + sw256(browb[g] + kk2 * 64));
#pragma unroll
            for (int sub = 0; sub < 2; sub++) {
                int k = kk2 * 2 + sub;
                uint32_t aa[2][4];
#pragma unroll
                for (int f = 0; f < 2; f++)
                    LDSM4(aa[f], Xb + sw256(arowb[f] + k * 32));
#pragma unroll
                for (int f = 0; f < 2; f++)
#pragma unroll
                    for (int g = 0; g < 4; g++)
                        mma_tf32(acc[f][g], aa[f], &bb[g][sub * 2]);
            }
        }
        // single-barrier mainloop
    }

#pragma unroll
    for (int f = 0; f < 2; f++)
#pragma unroll
        for (int g = 0; g < 4; g++) {
            int m = wr * 32 + f * 16 + (l >> 2);
            int nn = wc * 32 + g * 8 + (l & 3) * 2;
            int gm = ti * 128 + m, gn = tj * 128 + nn;
            *reinterpret_cast<float2*>(&g_part[s][b][gm][gn]) =
                make_float2(acc[f][g][0], acc[f][g][1]);
            *reinterpret_cast<float2*>(&g_part[s][b][gm + 8][gn]) =
                make_float2(acc[f][g][2], acc[f][g][3]);
        }
}

// ---------------- Kernel 2: deterministic split reduction + mirror ---------
__global__ void __launch_bounds__(256) reduce_kernel() {
    int gid = blockIdx.x * 256 + threadIdx.x;
    int b  = gid >> 16;
    int ij = gid & 65535;
    int i  = ij >> 8;
    int j  = ij & 255;
    int si = i, sj = j;
    if (i >= 128 && j < 128) { si = j; sj = i; }
    float acc = 0.0f;
#pragma unroll
    for (int s = 0; s < SPLITS; s++) acc += g_part[s][b][si][sj];
    g_G[b][i][j] = acc;
}

// ---------------- Kernel 2b: parallel row sums ----------------
__global__ void __launch_bounds__(256) rowsum_kernel(const float* __restrict__ pos) {
    int mode = blockIdx.x;
    int part = blockIdx.y;
    int j = threadIdx.x;
    double acc = 0.0;
    if (mode == 0) {
        float px = pos[j * 3 + 0], py = pos[j * 3 + 1], pz = pos[j * 3 + 2];
        float pn = px * px + py * py + pz * pz;
        for (int i = part * 32; i < part * 32 + 32; i++) {
            float qx = pos[i * 3 + 0], qy = pos[i * 3 + 1], qz = pos[i * 3 + 2];
            float qn = qx * qx + qy * qy + qz * qz;
            float d2 = qn + pn - 2.0f * (qx * px + qy * py + qz * pz);
            acc += (double)sqrtf(fmaxf(d2, 0.0f));
        }
    } else {
        const float* Gb = &g_G[mode - 1][0][0];
        float nj = Gb[j * 256 + j];
        for (int i = part * 32; i < part * 32 + 32; i++) {
            float d2 = Gb[i * 256 + i] + nj - 2.0f * Gb[i * 256 + j];
            acc += (double)sqrtf(fmaxf(d2, 0.0f));
        }
    }
    g_rowpart[mode][part][j] = acc;
}

// ---------------- block argmax via shuffles (first-index tie-break) --------
// Lexicographic max on (v, -idx): associative & commutative -> deterministic.
__device__ __forceinline__ int block_argmax256(double v, int idx,
                                               double* s_v, int* s_i, int* s_res, int j) {
#pragma unroll
    for (int off = 16; off > 0; off >>= 1) {
        double ov = __shfl_down_sync(0xffffffffu, v, off);
        int    oi = __shfl_down_sync(0xffffffffu, idx, off);
        if (ov > v || (ov == v && oi < idx)) { v = ov; idx = oi; }
    }
    if ((j & 31) == 0) { s_v[j >> 5] = v; s_i[j >> 5] = idx; }
    __syncthreads();
    if (j < 8) {
        v = s_v[j]; idx = s_i[j];
#pragma unroll
        for (int off = 4; off > 0; off >>= 1) {
            double ov = __shfl_down_sync(0xffu, v, off, 8);
            int    oi = __shfl_down_sync(0xffu, idx, off, 8);
            if (ov > v || (ov == v && oi < idx)) { v = ov; idx = oi; }
        }
        if (j == 0) *s_res = idx;
    }
    __syncthreads();
    return *s_res;
}

// ---------------- Kernel 3: farthest point sampling (shfl argmax) ---------
__global__ void __launch_bounds__(256) fps_kernel(const float* __restrict__ pos) {
    int j = threadIdx.x;
    int mode = blockIdx.x;
    __shared__ double s_v[8];
    __shared__ int    s_i[8];
    __shared__ int    s_res;
    __shared__ float  spx[256], spy[256], spz[256], snrm[256];
    __shared__ int    ssel[NKCLUST];

    const float* Gb = nullptr;
    if (mode == 0) {
        spx[j] = pos[j * 3 + 0]; spy[j] = pos[j * 3 + 1]; spz[j] = pos[j * 3 + 2];
    } else {
        Gb = &g_G[mode - 1][0][0];
    }
    __syncthreads();
    if (mode == 0) snrm[j] = spx[j] * spx[j] + spy[j] * spy[j] + spz[j] * spz[j];
    else           snrm[j] = Gb[j * 256 + j];
    __syncthreads();

    auto dist = [&](int i) -> float {
        float d2;
        if (mode == 0) {
            float dot = spx[i] * spx[j] + spy[i] * spy[j] + spz[i] * spz[j];
            d2 = snrm[i] + snrm[j] - 2.0f * dot;
        } else {
            d2 = snrm[i] + snrm[j] - 2.0f * Gb[i * 256 + j];
        }
        return sqrtf(fmaxf(d2, 0.0f));
    };

    double rs = 0.0;
#pragma unroll
    for (int p = 0; p < 8; p++) rs += g_rowpart[mode][p][j];
    int cur = block_argmax256(rs, j, s_v, s_i, &s_res, j);
    if (j == 0) ssel[0] = cur;
    float mind = dist(cur);

    for (int it = 1; it < NKCLUST; it++) {
        cur = block_argmax256((double)mind, j, s_v, s_i, &s_res, j);
        if (j == 0) ssel[it] = cur;
        mind = fminf(mind, dist(cur));
    }
    __syncthreads();
    if (j < NKCLUST) {
        if (mode == 0) g_selpos[j] = ssel[j];
        else           g_sel[mode - 1][j] = ssel[j];
    }
}

// ---------------- Kernel 4: fused assign + update + final ----------------
__global__ void __launch_bounds__(512) tail_kernel(const float* __restrict__ pos,
                                                   float* __restrict__ out) {
    __shared__ float spos[NB * NC * 3];
    __shared__ float scx[NB][NKCLUST], scy[NB][NKCLUST], scz[NB][NKCLUST], scn[NB][NKCLUST];
    __shared__ int   sta[NB * NC];
    __shared__ float ax[NKCLUST], ay[NKCLUST], az[NKCLUST], an[NKCLUST];
    __shared__ float fcx[NKCLUST], fcy[NKCLUST], fcz[NKCLUST], fcn[NKCLUST];
    __shared__ unsigned char sord[256][NKCLUST];
    __shared__ int scounts[NKCLUST];

    int t = threadIdx.x;
    for (int i = t; i < NB * NC * 3; i += 512) spos[i] = pos[i];
    if (t < NKCLUST) scounts[t] = 0;
    __syncthreads();

    if (t < NB * NKCLUST) {
        int b = t >> 4, k = t & 15;
        int si = g_sel[b][k];
        float x = spos[(b * 256 + si) * 3 + 0];
        float y = spos[(b * 256 + si) * 3 + 1];
        float z = spos[(b * 256 + si) * 3 + 2];
        scx[b][k] = x; scy[b][k] = y; scz[b][k] = z; scn[b][k] = x * x + y * y + z * z;
    }
    __syncthreads();

    for (int p = t; p < NB * NC; p += 512) {
        int b = p >> 8;
        float px = spos[p * 3 + 0], py = spos[p * 3 + 1], pz = spos[p * 3 + 2];
        float pn = px * px + py * py + pz * pz;
        float best = 1e30f; int bi = 0;
        for (int k = 0; k < NKCLUST; k++) {
            float d2 = pn + scn[b][k] - 2.0f * (px * scx[b][k] + py * scy[b][k] + pz * scz[b][k]);
            float d = sqrtf(fmaxf(d2, 0.0f));
            if (d < best) { best = d; bi = k; }
        }
        sta[p] = bi;
    }
    __syncthreads();

    int wid = t >> 5, l = t & 31;
    if (wid < NKCLUST) {
        float sx = 0.f, sy = 0.f, sz = 0.f, cnt = 0.f;
        for (int p = l; p < NB * NC; p += 32) {
            if (sta[p] == wid) {
                sx += spos[p * 3 + 0]; sy += spos[p * 3 + 1]; sz += spos[p * 3 + 2];
                cnt += 1.0f;
            }
        }
#pragma unroll
        for (int off = 16; off > 0; off >>= 1) {
            sx  += __shfl_down_sync(0xffffffffu, sx,  off);
            sy  += __shfl_down_sync(0xffffffffu, sy,  off);
            sz  += __shfl_down_sync(0xffffffffu, sz,  off);
            cnt += __shfl_down_sync(0xffffffffu, cnt, off);
        }
        if (l == 0) {
            if (cnt > 0.f) {
                float dn = fmaxf(cnt, 1.0f);
                ax[wid] = sx / dn; ay[wid] = sy / dn; az[wid] = sz / dn;
            } else { ax[wid] = 0.f; ay[wid] = 0.f; az[wid] = 0.f; }
            an[wid] = ax[wid] * ax[wid] + ay[wid] * ay[wid] + az[wid] * az[wid];
        }
    }
    __syncthreads();

    if (t < NKCLUST) {
        int si = g_selpos[t];
        float cx = spos[si * 3 + 0], cy = spos[si * 3 + 1], cz = spos[si * 3 + 2];
        float cnrm = cx * cx + cy * cy + cz * cz;
        float best = 1e30f; int bm = 0;
        for (int m = 0; m < NKCLUST; m++) {
            float d2 = cnrm + an[m] - 2.0f * (cx * ax[m] + cy * ay[m] + cz * az[m]);
            float d = sqrtf(fmaxf(d2, 0.0f));
            if (d < best) { best = d; bm = m; }
        }
        float nx = 0.8f * cx + 0.2f * ax[bm];
        float ny = 0.8f * cy + 0.2f * ay[bm];
        float nz = 0.8f * cz + 0.2f * az[bm];
        fcx[t] = nx; fcy[t] = ny; fcz[t] = nz; fcn[t] = nx * nx + ny * ny + nz * nz;
    }
    __syncthreads();

    if (t < 256) {
        float px = spos[t * 3 + 0], py = spos[t * 3 + 1], pz = spos[t * 3 + 2];
        float pn = px * px + py * py + pz * pz;
        float d[NKCLUST];
        int ord[NKCLUST];
        for (int k = 0; k < NKCLUST; k++) {
            float d2 = pn + fcn[k] - 2.0f * (px * fcx[k] + py * fcy[k] + pz * fcz[k]);
            d[k] = sqrtf(fmaxf(d2, 0.0f));
            ord[k] = k;
        }
        for (int a = 1; a < NKCLUST; a++) {
            int key = ord[a]; float kd = d[key];
            int bq = a - 1;
            while (bq >= 0 && d[ord[bq]] > kd) { ord[bq + 1] = ord[bq]; bq--; }
            ord[bq + 1] = key;
        }
        for (int k = 0; k < NKCLUST; k++) sord[t][k] = (unsigned char)ord[k];
    }
    __syncthreads();

    if (t == 0) {
        for (int rr = 0; rr < 256; rr++) {
            int chosen = sord[rr][0];
            for (int k = 0; k < NKCLUST; k++) {
                int cid = sord[rr][k];
                if (scounts[cid] < 16) { chosen = cid; break; }
            }
            scounts[chosen]++;
            out[rr] = (float)chosen;
        }
    }
}

// ---------------- launch ----------------
extern "C" void kernel_launch(void* const* d_in, const int* in_sizes, int n_in,
                              void* d_out, int out_size) {
    const float* features = nullptr;
    const float* pos = nullptr;
    for (int i = 0; i < n_in; i++) {
        if (in_sizes[i] == NB * NC * KDIM)   features = (const float*)d_in[i];
        else if (in_sizes[i] == NB * NC * 3) pos      = (const float*)d_in[i];
    }
    if (!features) features = (const float*)d_in[0];
    if (!pos)      pos      = (const float*)d_in[1];
    float* out = (float*)d_out;

    cudaFuncSetAttribute(gram_mma, cudaFuncAttributeMaxDynamicSharedMemorySize, SM_TOTAL);

    // slot-alignment: gram stays the 4th launch (ncu-profiled slot)
    dummy_kernel<<<1, 32>>>();
    dummy_kernel<<<1, 32>>>();
    dummy_kernel<<<1, 32>>>();
    dim3 g1(3, SPLITS, NB);
    gram_mma<<<g1, GT, SM_TOTAL>>>(features);
    reduce_kernel<<<(NB * NC * NC) / 256, 256>>>();
    dim3 g2(9, 8);
    rowsum_kernel<<<g2, 256>>>(pos);
    fps_kernel<<<9, 256>>>(pos);
    tail_kernel<<<1, 512>>>(pos, out);
}